// round 1
// baseline (speedup 1.0000x reference)
#include <cuda_runtime.h>
#include <cuda_bf16.h>

// BoxDecoder: anchor decode + score-threshold mask.
// out layout (f32): [ box_tensor (B*A*C*6) | mask (B*A*C) | batch_index (B*A*C) ]
//
// One thread per (b, a). C specialized to 8 (production shape) with a
// generic fallback. All wide loads/stores are 16B-aligned float4.

__global__ void __launch_bounds__(256)
box_decode_c8_kernel(const float* __restrict__ anchors,   // [A,4] cx,cy,w,h
                     const float* __restrict__ loc,       // [B,A,4]
                     const float* __restrict__ cls,       // [B,A,8]
                     const float* __restrict__ varx_p,
                     const float* __restrict__ vary_p,
                     const float* __restrict__ thr_p,
                     float* __restrict__ out_box,         // [B*A*8, 6]
                     float* __restrict__ out_mask,        // [B*A*8] (may be null)
                     float* __restrict__ out_bidx,        // [B*A*8] (may be null)
                     int A, long long total)              // total = B*A
{
    long long t = (long long)blockIdx.x * blockDim.x + threadIdx.x;
    if (t >= total) return;

    const float varx = *varx_p;
    const float vary = *vary_p;
    const float thr  = *thr_p;

    int b = (int)(t / A);
    int a = (int)(t - (long long)b * A);

    float4 anc = __ldg((const float4*)anchors + a);        // cx,cy,w,h
    float4 lp  = __ldg((const float4*)loc + t);

    float cx = lp.x * varx * anc.z + anc.x;
    float cy = lp.y * varx * anc.w + anc.y;
    float w  = expf(lp.z * vary) * anc.z;
    float h  = expf(lp.w * vary) * anc.w;

    float x0 = cx - 0.5f * w;
    float y0 = cy - 0.5f * h;
    float x1 = cx + 0.5f * w;
    float y1 = cy + 0.5f * h;

    // scores: 8 contiguous floats, 16B aligned (t*8 floats)
    float4 s01 = __ldg((const float4*)cls + t * 2);
    float4 s23 = __ldg((const float4*)cls + t * 2 + 1);
    float s[8] = { s01.x, s01.y, s01.z, s01.w, s23.x, s23.y, s23.z, s23.w };

    // box_tensor: 8 rows of 6 floats = 48 floats = 12 float4, contiguous & aligned
    float4* bo = (float4*)(out_box + t * 48);
#pragma unroll
    for (int p = 0; p < 4; p++) {           // pairs of classes (2*p, 2*p+1)
        float sA = s[2 * p];
        float sB = s[2 * p + 1];
        float lA = (float)(2 * p + 1);       // label = c+1
        float lB = (float)(2 * p + 2);
        bo[3 * p + 0] = make_float4(x0, y0, x1, y1);
        bo[3 * p + 1] = make_float4(sA, lA, x0, y0);
        bo[3 * p + 2] = make_float4(x1, y1, sB, lB);
    }

    if (out_mask) {
        float m[8];
#pragma unroll
        for (int c = 0; c < 8; c++) m[c] = (s[c] >= thr) ? 1.0f : 0.0f;
        float4* mo = (float4*)(out_mask + t * 8);
        mo[0] = make_float4(m[0], m[1], m[2], m[3]);
        mo[1] = make_float4(m[4], m[5], m[6], m[7]);
    }

    if (out_bidx) {
        float bf = (float)b;
        float4* io = (float4*)(out_bidx + t * 8);
        float4 v = make_float4(bf, bf, bf, bf);
        io[0] = v;
        io[1] = v;
    }
}

// Generic-C fallback (scalar stores), in case C != 8.
__global__ void __launch_bounds__(256)
box_decode_generic_kernel(const float* __restrict__ anchors,
                          const float* __restrict__ loc,
                          const float* __restrict__ cls,
                          const float* __restrict__ varx_p,
                          const float* __restrict__ vary_p,
                          const float* __restrict__ thr_p,
                          float* __restrict__ out_box,
                          float* __restrict__ out_mask,
                          float* __restrict__ out_bidx,
                          int A, int C, long long total)
{
    long long t = (long long)blockIdx.x * blockDim.x + threadIdx.x;
    if (t >= total) return;

    const float varx = *varx_p;
    const float vary = *vary_p;
    const float thr  = *thr_p;

    int b = (int)(t / A);
    int a = (int)(t - (long long)b * A);

    float4 anc = __ldg((const float4*)anchors + a);
    float4 lp  = __ldg((const float4*)loc + t);

    float cx = lp.x * varx * anc.z + anc.x;
    float cy = lp.y * varx * anc.w + anc.y;
    float w  = expf(lp.z * vary) * anc.z;
    float h  = expf(lp.w * vary) * anc.w;

    float x0 = cx - 0.5f * w;
    float y0 = cy - 0.5f * h;
    float x1 = cx + 0.5f * w;
    float y1 = cy + 0.5f * h;

    for (int c = 0; c < C; c++) {
        long long r = t * C + c;
        float sc = cls[r];
        float* row = out_box + r * 6;
        row[0] = x0; row[1] = y0; row[2] = x1; row[3] = y1;
        row[4] = sc; row[5] = (float)(c + 1);
        if (out_mask) out_mask[r] = (sc >= thr) ? 1.0f : 0.0f;
        if (out_bidx) out_bidx[r] = (float)b;
    }
}

extern "C" void kernel_launch(void* const* d_in, const int* in_sizes, int n_in,
                              void* d_out, int out_size)
{
    // Input order per setup_inputs: anchors, loc_preds, cls_preds,
    // varx, vary, score_thresh, batch_size
    const float* anchors = (const float*)d_in[0];
    const float* loc     = (const float*)d_in[1];
    const float* cls     = (const float*)d_in[2];
    const float* varx_p  = (const float*)d_in[3];
    const float* vary_p  = (const float*)d_in[4];
    const float* thr_p   = (const float*)d_in[5];

    const long long A   = in_sizes[0] / 4;
    const long long B   = in_sizes[1] / (A * 4);
    const long long C   = in_sizes[2] / (B * A);
    const long long BAC = B * A * C;
    const long long total = B * A;

    float* out = (float*)d_out;
    float* out_box  = out;                                        // BAC*6
    float* out_mask = (out_size >= (long long)(BAC * 7)) ? out + BAC * 6 : nullptr;
    float* out_bidx = (out_size >= (long long)(BAC * 8)) ? out + BAC * 7 : nullptr;

    // Hedge: if the harness allocated more than we write, clear the tail
    // (d_out is poisoned to 0xAA). Graph-capturable async memset.
    long long written = BAC * 6;
    if (out_mask) written = BAC * 7;
    if (out_bidx) written = BAC * 8;
    if ((long long)out_size > written) {
        cudaMemsetAsync(out + written, 0,
                        ((long long)out_size - written) * sizeof(float));
    }

    const int threads = 256;
    const long long blocks = (total + threads - 1) / threads;

    if (C == 8) {
        box_decode_c8_kernel<<<(unsigned)blocks, threads>>>(
            anchors, loc, cls, varx_p, vary_p, thr_p,
            out_box, out_mask, out_bidx, (int)A, total);
    } else {
        box_decode_generic_kernel<<<(unsigned)blocks, threads>>>(
            anchors, loc, cls, varx_p, vary_p, thr_p,
            out_box, out_mask, out_bidx, (int)A, (int)C, total);
    }
}

// round 2
// speedup vs baseline: 2.1173x; 2.1173x over previous
#include <cuda_runtime.h>
#include <cuda_bf16.h>

// BoxDecoder: anchor decode + score-threshold mask.
// out layout (f32): [ box_tensor (B*A*C*6) | mask (B*A*C) | batch_index (B*A*C) ]
//
// R2: all global stores coalesced.
//  - box rows staged in padded smem (stride 52 floats -> conflict-free STS.128),
//    then copied out as contiguous float4s.
//  - mask is elementwise over cls at the same flat index -> direct coalesced pass.
//  - batch_index derived from the flat index -> direct coalesced pass.

constexpr int TPB = 128;          // threads per block == t-tiles per block
constexpr int ROW = 52;           // padded smem row stride in floats (48 data + 4 pad)

__global__ void __launch_bounds__(TPB)
box_decode_c8_kernel(const float* __restrict__ anchors,   // [A,4] cx,cy,w,h
                     const float* __restrict__ loc,       // [B,A,4]
                     const float* __restrict__ cls,       // [B,A,8]
                     const float* __restrict__ varx_p,
                     const float* __restrict__ vary_p,
                     const float* __restrict__ thr_p,
                     float* __restrict__ out_box,         // [B*A*8, 6]
                     float* __restrict__ out_mask,        // [B*A*8] or null
                     float* __restrict__ out_bidx,        // [B*A*8] or null
                     int A, long long total)              // total = B*A
{
    __shared__ float sm[TPB * ROW];

    const long long bs = (long long)blockIdx.x * TPB;   // first t of this block
    const int tid = threadIdx.x;
    const long long t = bs + tid;

    const float varx = *varx_p;
    const float vary = *vary_p;
    const float thr  = *thr_p;

    // ---- mask: elementwise over cls float4s, perfectly coalesced ----
    // float4 index j covers classes of t = j/2. Block owns j in [bs*2, bs*2+2*TPB).
    if (out_mask) {
#pragma unroll
        for (int k = 0; k < 2; k++) {
            long long j = bs * 2 + (long long)k * TPB + tid;
            if (j < total * 2) {
                float4 sv = __ldg((const float4*)cls + j);
                ((float4*)out_mask)[j] = make_float4(
                    sv.x >= thr ? 1.0f : 0.0f,
                    sv.y >= thr ? 1.0f : 0.0f,
                    sv.z >= thr ? 1.0f : 0.0f,
                    sv.w >= thr ? 1.0f : 0.0f);
            }
        }
    }

    // ---- batch_index: derived from index, coalesced ----
    if (out_bidx) {
#pragma unroll
        for (int k = 0; k < 2; k++) {
            long long j = bs * 2 + (long long)k * TPB + tid;  // float4 idx, t2 = j/2
            if (j < total * 2) {
                float bf = (float)(int)((j >> 1) / A);
                ((float4*)out_bidx)[j] = make_float4(bf, bf, bf, bf);
            }
        }
    }

    // ---- phase 1: decode own t, stage 48 floats into padded smem row ----
    if (t < total) {
        int b_unused;
        (void)b_unused;
        int a = (int)(t % A);

        float4 anc = __ldg((const float4*)anchors + a);   // cx,cy,w,h
        float4 lp  = __ldg((const float4*)loc + t);

        float cx = lp.x * varx * anc.z + anc.x;
        float cy = lp.y * varx * anc.w + anc.y;
        float w  = __expf(lp.z * vary) * anc.z;
        float h  = __expf(lp.w * vary) * anc.w;

        float x0 = cx - 0.5f * w;
        float y0 = cy - 0.5f * h;
        float x1 = cx + 0.5f * w;
        float y1 = cy + 0.5f * h;

        float4 s01 = __ldg((const float4*)cls + t * 2);
        float4 s23 = __ldg((const float4*)cls + t * 2 + 1);
        float s[8] = { s01.x, s01.y, s01.z, s01.w, s23.x, s23.y, s23.z, s23.w };

        float4* row = (float4*)(sm + tid * ROW);   // 208B stride, 16B aligned
#pragma unroll
        for (int p = 0; p < 4; p++) {              // class pair (2p, 2p+1)
            row[3 * p + 0] = make_float4(x0, y0, x1, y1);
            row[3 * p + 1] = make_float4(s[2 * p], (float)(2 * p + 1), x0, y0);
            row[3 * p + 2] = make_float4(x1, y1, s[2 * p + 1], (float)(2 * p + 2));
        }
    }
    __syncthreads();

    // ---- phase 2: coalesced copy smem -> gmem (12 float4 per thread) ----
    const int nvalid = (int)min((long long)TPB, total - bs);
    const int nf4 = nvalid * 12;
    float4* dst = (float4*)out_box + bs * 12;
#pragma unroll
    for (int k = 0; k < 12; k++) {
        int i = tid + k * TPB;                     // logical float4 index in tile
        if (i < nf4) {
            int tl  = i / 12;
            int pos = i - tl * 12;
            dst[i] = *(const float4*)(sm + tl * ROW + pos * 4);
        }
    }
}

// Generic-C fallback (scalar stores), in case C != 8.
__global__ void __launch_bounds__(256)
box_decode_generic_kernel(const float* __restrict__ anchors,
                          const float* __restrict__ loc,
                          const float* __restrict__ cls,
                          const float* __restrict__ varx_p,
                          const float* __restrict__ vary_p,
                          const float* __restrict__ thr_p,
                          float* __restrict__ out_box,
                          float* __restrict__ out_mask,
                          float* __restrict__ out_bidx,
                          int A, int C, long long total)
{
    long long t = (long long)blockIdx.x * blockDim.x + threadIdx.x;
    if (t >= total) return;

    const float varx = *varx_p;
    const float vary = *vary_p;
    const float thr  = *thr_p;

    int b = (int)(t / A);
    int a = (int)(t - (long long)b * A);

    float4 anc = __ldg((const float4*)anchors + a);
    float4 lp  = __ldg((const float4*)loc + t);

    float cx = lp.x * varx * anc.z + anc.x;
    float cy = lp.y * varx * anc.w + anc.y;
    float w  = expf(lp.z * vary) * anc.z;
    float h  = expf(lp.w * vary) * anc.w;

    float x0 = cx - 0.5f * w;
    float y0 = cy - 0.5f * h;
    float x1 = cx + 0.5f * w;
    float y1 = cy + 0.5f * h;

    for (int c = 0; c < C; c++) {
        long long r = t * C + c;
        float sc = cls[r];
        float* row = out_box + r * 6;
        row[0] = x0; row[1] = y0; row[2] = x1; row[3] = y1;
        row[4] = sc; row[5] = (float)(c + 1);
        if (out_mask) out_mask[r] = (sc >= thr) ? 1.0f : 0.0f;
        if (out_bidx) out_bidx[r] = (float)b;
    }
}

extern "C" void kernel_launch(void* const* d_in, const int* in_sizes, int n_in,
                              void* d_out, int out_size)
{
    // Input order per setup_inputs: anchors, loc_preds, cls_preds,
    // varx, vary, score_thresh, batch_size
    const float* anchors = (const float*)d_in[0];
    const float* loc     = (const float*)d_in[1];
    const float* cls     = (const float*)d_in[2];
    const float* varx_p  = (const float*)d_in[3];
    const float* vary_p  = (const float*)d_in[4];
    const float* thr_p   = (const float*)d_in[5];

    const long long A   = in_sizes[0] / 4;
    const long long B   = in_sizes[1] / (A * 4);
    const long long C   = in_sizes[2] / (B * A);
    const long long BAC = B * A * C;
    const long long total = B * A;

    float* out = (float*)d_out;
    float* out_box  = out;                                        // BAC*6
    float* out_mask = (out_size >= (long long)(BAC * 7)) ? out + BAC * 6 : nullptr;
    float* out_bidx = (out_size >= (long long)(BAC * 8)) ? out + BAC * 7 : nullptr;

    // Hedge: if the harness allocated more than we write, clear the tail
    // (d_out is poisoned to 0xAA). Graph-capturable async memset.
    long long written = BAC * 6;
    if (out_mask) written = BAC * 7;
    if (out_bidx) written = BAC * 8;
    if ((long long)out_size > written) {
        cudaMemsetAsync(out + written, 0,
                        ((long long)out_size - written) * sizeof(float));
    }

    if (C == 8) {
        const long long blocks = (total + TPB - 1) / TPB;
        box_decode_c8_kernel<<<(unsigned)blocks, TPB>>>(
            anchors, loc, cls, varx_p, vary_p, thr_p,
            out_box, out_mask, out_bidx, (int)A, total);
    } else {
        const int threads = 256;
        const long long blocks = (total + threads - 1) / threads;
        box_decode_generic_kernel<<<(unsigned)blocks, threads>>>(
            anchors, loc, cls, varx_p, vary_p, thr_p,
            out_box, out_mask, out_bidx, (int)A, (int)C, total);
    }
}